// round 4
// baseline (speedup 1.0000x reference)
#include <cuda_runtime.h>
#include <stdint.h>

// ---------------------------------------------------------------------------
// PillarMotionNet voxelization: key/histogram/scan/feature pipeline.
//   points: (N, 6) float32 rows [batch, x, y, z, intensity, time]
//   out   : [features (N*9) | unq (N*4) | unq_inv (N) | grid (3)] float32
// Grid: 400 x 400, 4 batches, 5 time steps -> 3,200,000 possible keys.
// ---------------------------------------------------------------------------

#define GX 400
#define GY 400
#define NTIME 5
#define NBATCH 4
#define NKEYS (NBATCH * GX * GY * NTIME)   // 3,200,000
#define MAXPTS 2000000
#define SCAN_BLOCK 1024
#define NSCANBLK (NKEYS / SCAN_BLOCK)      // 3125 (exact)

// __device__ global scratch (allocation-free rule)
__device__ int   g_counts[NKEYS];
__device__ float g_sumx[NKEYS];
__device__ float g_sumy[NKEYS];
__device__ float g_sumz[NKEYS];
__device__ int   g_rank[NKEYS];
__device__ int   g_key[MAXPTS];
__device__ int   g_blockCnt[NSCANBLK];
__device__ int   g_blockOff[NSCANBLK];

// ---------------------------------------------------------------------------
// 1) Zero scratch, fill unq region with -1, write grid_size tail.
// ---------------------------------------------------------------------------
__global__ void k_init(float* __restrict__ out_unq, float* __restrict__ out_grid,
                       int n4) {
    int i = blockIdx.x * blockDim.x + threadIdx.x;
    if (i < NKEYS) {
        g_counts[i] = 0;
        g_sumx[i] = 0.0f;
        g_sumy[i] = 0.0f;
        g_sumz[i] = 0.0f;
    }
    if (i < n4) out_unq[i] = -1.0f;
    if (i == 0) {
        out_grid[0] = (float)GX;
        out_grid[1] = (float)GY;
        out_grid[2] = 1.0f;
    }
}

// ---------------------------------------------------------------------------
// 2) Per-point: compute key, histogram + xyz sums (atomics land in L2).
// ---------------------------------------------------------------------------
__global__ void k_accum(const float* __restrict__ pts, int N) {
    int i = blockIdx.x * blockDim.x + threadIdx.x;
    if (i >= N) return;
    const float* p = pts + (size_t)i * 6;
    float b_f = p[0], x = p[1], y = p[2], z = p[3], t_f = p[5];
    // coords = trunc((p - pc_min) / voxel); division by 0.25 == *4 exactly
    int cx = (int)((x + 50.0f) * 4.0f);
    int cy = (int)((y + 50.0f) * 4.0f);
    int b  = (int)b_f;
    int t  = (int)t_f;
    int key = ((b * GX + cx) * GY + cy) * NTIME + t;
    g_key[i] = key;
    atomicAdd(&g_counts[key], 1);
    atomicAdd(&g_sumx[key], x);
    atomicAdd(&g_sumy[key], y);
    atomicAdd(&g_sumz[key], z);
}

// ---------------------------------------------------------------------------
// 3a) Occupancy count per scan-block (1024 keys per block).
// ---------------------------------------------------------------------------
__global__ void k_scan1() {
    int i = blockIdx.x * SCAN_BLOCK + threadIdx.x;
    int flag = (g_counts[i] > 0) ? 1 : 0;
    unsigned m = __ballot_sync(0xffffffffu, flag);
    __shared__ int wsum[32];
    int lane = threadIdx.x & 31, warp = threadIdx.x >> 5;
    if (lane == 0) wsum[warp] = __popc(m);
    __syncthreads();
    if (threadIdx.x < 32) {
        int v = wsum[threadIdx.x];
        #pragma unroll
        for (int off = 16; off > 0; off >>= 1)
            v += __shfl_down_sync(0xffffffffu, v, off);
        if (threadIdx.x == 0) g_blockCnt[blockIdx.x] = v;
    }
}

// ---------------------------------------------------------------------------
// 3b) Single-block exclusive scan of 3125 block counts.
// ---------------------------------------------------------------------------
__global__ void k_scan2() {
    __shared__ int sh[1024];
    const int ITEMS = (NSCANBLK + 1023) / 1024;  // 4
    int tid = threadIdx.x;
    int base = tid * ITEMS;
    int local[ITEMS];
    int s = 0;
    #pragma unroll
    for (int j = 0; j < ITEMS; j++) {
        int idx = base + j;
        int v = (idx < NSCANBLK) ? g_blockCnt[idx] : 0;
        local[j] = v;
        s += v;
    }
    sh[tid] = s;
    __syncthreads();
    // Hillis-Steele inclusive scan
    for (int off = 1; off < 1024; off <<= 1) {
        int v = (tid >= off) ? sh[tid - off] : 0;
        __syncthreads();
        sh[tid] += v;
        __syncthreads();
    }
    int run = sh[tid] - s;  // exclusive prefix for this thread's chunk
    #pragma unroll
    for (int j = 0; j < ITEMS; j++) {
        int idx = base + j;
        if (idx < NSCANBLK) g_blockOff[idx] = run;
        run += local[j];
    }
}

// ---------------------------------------------------------------------------
// 3c) Write rank[key] = global exclusive prefix of occupancy flags.
// ---------------------------------------------------------------------------
__global__ void k_scan3() {
    int i = blockIdx.x * SCAN_BLOCK + threadIdx.x;
    int flag = (g_counts[i] > 0) ? 1 : 0;
    unsigned m = __ballot_sync(0xffffffffu, flag);
    int lane = threadIdx.x & 31, warp = threadIdx.x >> 5;
    int lanePrefix = __popc(m & ((1u << lane) - 1u));
    __shared__ int wcnt[32];
    if (lane == 0) wcnt[warp] = __popc(m);
    __syncthreads();
    if (threadIdx.x < 32) {
        int orig = wcnt[threadIdx.x];
        int v = orig;
        #pragma unroll
        for (int off = 1; off < 32; off <<= 1) {
            int u = __shfl_up_sync(0xffffffffu, v, off);
            if (lane >= off) v += u;
        }
        wcnt[threadIdx.x] = v - orig;  // exclusive
    }
    __syncthreads();
    if (flag) g_rank[i] = g_blockOff[blockIdx.x] + wcnt[warp] + lanePrefix;
}

// ---------------------------------------------------------------------------
// 4) Per-point feature emit (9 floats) + unq_inv.
// ---------------------------------------------------------------------------
__global__ void k_feat(const float* __restrict__ pts, float* __restrict__ out,
                       int N) {
    int i = blockIdx.x * blockDim.x + threadIdx.x;
    if (i >= N) return;
    const float* p = pts + (size_t)i * 6;
    float x = p[1], y = p[2], z = p[3], inten = p[4];
    int key = g_key[i];
    float cnt = (float)g_counts[key];
    float inv = 1.0f / cnt;
    float mx = g_sumx[key] * inv;
    float my = g_sumy[key] * inv;
    float mz = g_sumz[key] * inv;
    int cx = (int)((x + 50.0f) * 4.0f);
    int cy = (int)((y + 50.0f) * 4.0f);
    // f_center = p_xy - (coord*0.25 + 0.125 - 50)
    float fcx = x - ((float)cx * 0.25f + 0.125f - 50.0f);
    float fcy = y - ((float)cy * 0.25f + 0.125f - 50.0f);
    float* f = out + (size_t)i * 9;
    f[0] = x;
    f[1] = y;
    f[2] = z;
    f[3] = inten;
    f[4] = x - mx;
    f[5] = y - my;
    f[6] = z - mz;
    f[7] = fcx;
    f[8] = fcy;
    // unq_inv region at 13N
    out[(size_t)13 * N + i] = (float)g_rank[key];
}

// ---------------------------------------------------------------------------
// 5) Emit decoded (b, t, y, x) rows at their rank positions.
// ---------------------------------------------------------------------------
__global__ void k_unq(float* __restrict__ out, int N) {
    int k = blockIdx.x * blockDim.x + threadIdx.x;
    if (k >= NKEYS) return;
    if (g_counts[k] == 0) return;
    int r = g_rank[k];
    int key = k;
    int tt = key % NTIME; key /= NTIME;
    int yy = key % GY;    key /= GY;
    int xx = key % GX;
    int bb = key / GX;
    float* u = out + (size_t)9 * N + (size_t)r * 4;
    u[0] = (float)bb;
    u[1] = (float)tt;
    u[2] = (float)yy;
    u[3] = (float)xx;
}

// ---------------------------------------------------------------------------
extern "C" void kernel_launch(void* const* d_in, const int* in_sizes, int n_in,
                              void* d_out, int out_size) {
    const float* pts = (const float*)d_in[0];
    float* out = (float*)d_out;
    int N = in_sizes[0] / 6;
    int n4 = 4 * N;

    int initN = (NKEYS > n4) ? NKEYS : n4;
    k_init<<<(initN + 255) / 256, 256>>>(out + (size_t)9 * N,
                                         out + (size_t)14 * N, n4);
    k_accum<<<(N + 255) / 256, 256>>>(pts, N);
    k_scan1<<<NSCANBLK, SCAN_BLOCK>>>();
    k_scan2<<<1, 1024>>>();
    k_scan3<<<NSCANBLK, SCAN_BLOCK>>>();
    k_feat<<<(N + 255) / 256, 256>>>(pts, out, N);
    k_unq<<<(NKEYS + 255) / 256, 256>>>(out, N);
}

// round 7
// speedup vs baseline: 1.9394x; 1.9394x over previous
#include <cuda_runtime.h>
#include <stdint.h>

// ---------------------------------------------------------------------------
// PillarMotionNet voxelization, v2: vector atomics + occupancy bitmask +
// packed rank/count + smem-staged coalesced feature stores.
//   points: (N, 6) float32 rows [batch, x, y, z, intensity, time]
//   out   : [features (N*9) | unq (N*4) | unq_inv (N) | grid (3)] float32
// ---------------------------------------------------------------------------

#define GX 400
#define GY 400
#define NTIME 5
#define NBATCH 4
#define NKEYS (NBATCH * GX * GY * NTIME)   // 3,200,000
#define NWORDS (NKEYS / 32)                // 100,000
#define S1_BLOCK 256
#define NS1 ((NWORDS + S1_BLOCK - 1) / S1_BLOCK)  // 391

// __device__ global scratch (allocation-free rule)
__device__ float4   g_acc[NKEYS];     // {sum_x, sum_y, sum_z, count} -> .w repacked to (rank<<11|cnt)
__device__ unsigned g_mask[NWORDS];   // occupancy bitmask
__device__ int      g_blockCnt[NS1];
__device__ int      g_blockOff[NS1];
__device__ int      g_total;

// ---------------------------------------------------------------------------
// 1) Zero accumulator + bitmask. NKEYS = 12500 * 256 exactly.
// ---------------------------------------------------------------------------
__global__ void k_init() {
    int i = blockIdx.x * 256 + threadIdx.x;
    g_acc[i] = make_float4(0.0f, 0.0f, 0.0f, 0.0f);
    if (i < NWORDS) g_mask[i] = 0u;
}

// ---------------------------------------------------------------------------
// 2) Per-point: one v4 float RED + one bitmask OR.
// ---------------------------------------------------------------------------
__global__ void k_accum(const float* __restrict__ pts, int N) {
    int i = blockIdx.x * blockDim.x + threadIdx.x;
    if (i >= N) return;
    const float2* p2 = (const float2*)(pts + (size_t)i * 6);
    float2 a = __ldg(p2);        // {batch, x}
    float2 b = __ldg(p2 + 1);    // {y, z}
    float2 c = __ldg(p2 + 2);    // {intensity, time}
    float x = a.y, y = b.x, z = b.y;
    int cx = (int)((x + 50.0f) * 4.0f);
    int cy = (int)((y + 50.0f) * 4.0f);
    int key = (((int)a.x * GX + cx) * GY + cy) * NTIME + (int)c.y;
    float4* addr = &g_acc[key];
    asm volatile("red.global.add.v4.f32 [%0], {%1, %2, %3, %4};"
                 :: "l"(addr), "f"(x), "f"(y), "f"(z), "f"(1.0f) : "memory");
    atomicOr(&g_mask[key >> 5], 1u << (key & 31));
}

// ---------------------------------------------------------------------------
// 3a) Per-scan-block occupancy (popc over bitmask words).
// ---------------------------------------------------------------------------
__global__ void k_scan1() {
    int w = blockIdx.x * S1_BLOCK + threadIdx.x;
    int c = (w < NWORDS) ? __popc(g_mask[w]) : 0;
    #pragma unroll
    for (int o = 16; o > 0; o >>= 1) c += __shfl_down_sync(0xffffffffu, c, o);
    __shared__ int ws[8];
    int lane = threadIdx.x & 31, warp = threadIdx.x >> 5;
    if (lane == 0) ws[warp] = c;
    __syncthreads();
    if (threadIdx.x == 0) {
        int s = 0;
        #pragma unroll
        for (int k = 0; k < 8; k++) s += ws[k];
        g_blockCnt[blockIdx.x] = s;
    }
}

// ---------------------------------------------------------------------------
// 3b) Single-block exclusive scan of NS1 (=391) block counts.
// ---------------------------------------------------------------------------
__global__ void k_scan2() {
    __shared__ int sh[512];
    int tid = threadIdx.x;
    int v = (tid < NS1) ? g_blockCnt[tid] : 0;
    sh[tid] = v;
    __syncthreads();
    for (int o = 1; o < 512; o <<= 1) {
        int u = (tid >= o) ? sh[tid - o] : 0;
        __syncthreads();
        sh[tid] += u;
        __syncthreads();
    }
    if (tid < NS1) g_blockOff[tid] = sh[tid] - v;
    if (tid == 511) g_total = sh[511];
}

// ---------------------------------------------------------------------------
// 3c) Per occupied key: assign rank, repack acc.w = (rank<<11)|cnt, and emit
//     the decoded (b,t,y,x) unq row at its rank position (coalesced-ish).
// ---------------------------------------------------------------------------
__global__ void k_scan3(float* __restrict__ out_unq) {
    int w = blockIdx.x * S1_BLOCK + threadIdx.x;
    unsigned m = (w < NWORDS) ? g_mask[w] : 0u;
    int c = __popc(m);
    int lane = threadIdx.x & 31, warp = threadIdx.x >> 5;
    // intra-warp inclusive scan of c
    int v = c;
    #pragma unroll
    for (int o = 1; o < 32; o <<= 1) {
        int u = __shfl_up_sync(0xffffffffu, v, o);
        if (lane >= o) v += u;
    }
    __shared__ int ws[8];
    if (lane == 31) ws[warp] = v;
    __syncthreads();
    int wbase = 0;
    #pragma unroll
    for (int k = 0; k < 8; k++) wbase += (k < warp) ? ws[k] : 0;
    int rank = g_blockOff[blockIdx.x] + wbase + (v - c);  // exclusive prefix

    float4* u4 = (float4*)out_unq;
    while (m) {
        int b = __ffs(m) - 1;
        m &= m - 1;
        int key = w * 32 + b;
        int cnt = (int)g_acc[key].w;
        unsigned pk = ((unsigned)rank << 11) | (unsigned)cnt;
        g_acc[key].w = __int_as_float((int)pk);
        int k2 = key;
        int tt = k2 % NTIME; k2 /= NTIME;
        int yy = k2 % GY;    k2 /= GY;
        int xx = k2 % GX;
        int bb = k2 / GX;
        u4[rank] = make_float4((float)bb, (float)tt, (float)yy, (float)xx);
        rank++;
    }
}

// ---------------------------------------------------------------------------
// 4) Per-point features (smem-staged float4 stores) + unq_inv + tail -1 fill
//    + grid_size output.
// ---------------------------------------------------------------------------
__global__ void k_feat(const float* __restrict__ pts, float* __restrict__ out,
                       int N) {
    __shared__ float sf[256 * 9];
    int i = blockIdx.x * 256 + threadIdx.x;
    bool act = (i < N);
    float r[9] = {0, 0, 0, 0, 0, 0, 0, 0, 0};
    int rankv = 0;
    if (act) {
        const float2* p2 = (const float2*)(pts + (size_t)i * 6);
        float2 a = __ldg(p2);
        float2 b = __ldg(p2 + 1);
        float2 c = __ldg(p2 + 2);
        float x = a.y, y = b.x, z = b.y, inten = c.x;
        int cx = (int)((x + 50.0f) * 4.0f);
        int cy = (int)((y + 50.0f) * 4.0f);
        int key = (((int)a.x * GX + cx) * GY + cy) * NTIME + (int)c.y;
        float4 g = __ldg(&g_acc[key]);
        unsigned pk = (unsigned)__float_as_int(g.w);
        int cnt = (int)(pk & 2047u);
        rankv = (int)(pk >> 11);
        float inv = 1.0f / (float)cnt;
        r[0] = x; r[1] = y; r[2] = z; r[3] = inten;
        r[4] = x - g.x * inv;
        r[5] = y - g.y * inv;
        r[6] = z - g.z * inv;
        r[7] = x - ((float)cx * 0.25f - 49.875f);
        r[8] = y - ((float)cy * 0.25f - 49.875f);
    }
    #pragma unroll
    for (int j = 0; j < 9; j++) sf[threadIdx.x * 9 + j] = r[j];
    __syncthreads();

    size_t blockBase = (size_t)blockIdx.x * (256 * 9);
    if (blockBase + 256 * 9 <= (size_t)9 * N) {
        float4* o4 = (float4*)(out + blockBase);
        const float4* s4 = (const float4*)sf;
        for (int t = threadIdx.x; t < 576; t += 256) o4[t] = s4[t];
    } else if (act) {
        for (int j = 0; j < 9; j++) out[(size_t)i * 9 + j] = r[j];
    }

    if (act) {
        out[(size_t)13 * N + i] = (float)rankv;  // unq_inv
        int U = g_total;
        if (i >= U)
            ((float4*)(out + (size_t)9 * N))[i] = make_float4(-1.f, -1.f, -1.f, -1.f);
        if (i == 0) {
            float* gr = out + (size_t)14 * N;
            gr[0] = 400.0f; gr[1] = 400.0f; gr[2] = 1.0f;
        }
    }
}

// ---------------------------------------------------------------------------
extern "C" void kernel_launch(void* const* d_in, const int* in_sizes, int n_in,
                              void* d_out, int out_size) {
    const float* pts = (const float*)d_in[0];
    float* out = (float*)d_out;
    int N = in_sizes[0] / 6;

    k_init<<<NKEYS / 256, 256>>>();
    k_accum<<<(N + 255) / 256, 256>>>(pts, N);
    k_scan1<<<NS1, S1_BLOCK>>>();
    k_scan2<<<1, 512>>>();
    k_scan3<<<NS1, S1_BLOCK>>>(out + (size_t)9 * N);
    k_feat<<<(N + 255) / 256, 256>>>(pts, out, N);
}

// round 9
// speedup vs baseline: 2.0110x; 1.0369x over previous
#include <cuda_runtime.h>
#include <stdint.h>

// ---------------------------------------------------------------------------
// PillarMotionNet voxelization, v3: 2-pt vectorized accum, scan chain fused
// (each rank block self-computes its offset; no single-block scan kernel).
//   points: (N, 6) float32 rows [batch, x, y, z, intensity, time]
//   out   : [features (N*9) | unq (N*4) | unq_inv (N) | grid (3)] float32
// ---------------------------------------------------------------------------

#define GX 400
#define GY 400
#define NTIME 5
#define NBATCH 4
#define NKEYS (NBATCH * GX * GY * NTIME)   // 3,200,000
#define NWORDS (NKEYS / 32)                // 100,000
#define S1_BLOCK 256
#define NS1 ((NWORDS + S1_BLOCK - 1) / S1_BLOCK)  // 391

// __device__ global scratch (allocation-free rule)
__device__ float4   g_acc[NKEYS];     // {sx, sy, sz, cnt} -> .w repacked (rank<<11|cnt)
__device__ unsigned g_mask[NWORDS];   // occupancy bitmask
__device__ int      g_blockCnt[NS1];
__device__ int      g_total;

// ---------------------------------------------------------------------------
// 1) Zero accumulator + bitmask + total. NKEYS = 12500 * 256 exactly.
// ---------------------------------------------------------------------------
__global__ void k_init() {
    int i = blockIdx.x * 256 + threadIdx.x;
    g_acc[i] = make_float4(0.0f, 0.0f, 0.0f, 0.0f);
    if (i < NWORDS) g_mask[i] = 0u;
    if (i == 0) g_total = 0;
}

// ---------------------------------------------------------------------------
// 2) Two points per thread: 3 x float4 loads, v4 RED + bitmask OR each.
// ---------------------------------------------------------------------------
__device__ __forceinline__ void accum_one(float b_f, float x, float y, float z,
                                          float t_f) {
    int cx = (int)((x + 50.0f) * 4.0f);
    int cy = (int)((y + 50.0f) * 4.0f);
    int key = (((int)b_f * GX + cx) * GY + cy) * NTIME + (int)t_f;
    float4* addr = &g_acc[key];
    asm volatile("red.global.add.v4.f32 [%0], {%1, %2, %3, %4};"
                 :: "l"(addr), "f"(x), "f"(y), "f"(z), "f"(1.0f) : "memory");
    atomicOr(&g_mask[key >> 5], 1u << (key & 31));
}

__global__ void k_accum(const float* __restrict__ pts, int N) {
    int t = blockIdx.x * blockDim.x + threadIdx.x;
    int i0 = t * 2;
    if (i0 >= N) return;
    if (i0 + 1 < N) {
        const float4* q = (const float4*)(pts + (size_t)i0 * 6);
        float4 A = __ldg(q);       // b0 x0 y0 z0
        float4 B = __ldg(q + 1);   // i0 t0 b1 x1
        float4 C = __ldg(q + 2);   // y1 z1 i1 t1
        accum_one(A.x, A.y, A.z, A.w, B.y);
        accum_one(B.z, B.w, C.x, C.y, C.w);
    } else {
        const float* p = pts + (size_t)i0 * 6;
        accum_one(p[0], p[1], p[2], p[3], p[5]);
    }
}

// ---------------------------------------------------------------------------
// 3a) Per-scan-block occupancy count; accumulate grand total atomically.
// ---------------------------------------------------------------------------
__global__ void k_scan1() {
    int w = blockIdx.x * S1_BLOCK + threadIdx.x;
    int c = (w < NWORDS) ? __popc(g_mask[w]) : 0;
    #pragma unroll
    for (int o = 16; o > 0; o >>= 1) c += __shfl_down_sync(0xffffffffu, c, o);
    __shared__ int ws[8];
    int lane = threadIdx.x & 31, warp = threadIdx.x >> 5;
    if (lane == 0) ws[warp] = c;
    __syncthreads();
    if (threadIdx.x == 0) {
        int s = 0;
        #pragma unroll
        for (int k = 0; k < 8; k++) s += ws[k];
        g_blockCnt[blockIdx.x] = s;
        atomicAdd(&g_total, s);
    }
}

// ---------------------------------------------------------------------------
// 3b) Rank assignment + unq-row emission. Each block self-computes its
//     exclusive offset by summing g_blockCnt[0..bid) (<= 391 ints, trivial).
// ---------------------------------------------------------------------------
__global__ void k_scan3(float* __restrict__ out_unq) {
    __shared__ int red8[8];
    __shared__ int scan8[8];
    __shared__ int s_base;
    int lane = threadIdx.x & 31, warp = threadIdx.x >> 5;

    // exclusive block offset
    int partial = 0;
    for (int j = threadIdx.x; j < blockIdx.x; j += S1_BLOCK)
        partial += g_blockCnt[j];
    #pragma unroll
    for (int o = 16; o > 0; o >>= 1)
        partial += __shfl_down_sync(0xffffffffu, partial, o);
    if (lane == 0) red8[warp] = partial;
    __syncthreads();
    if (threadIdx.x == 0) {
        int s = 0;
        #pragma unroll
        for (int k = 0; k < 8; k++) s += red8[k];
        s_base = s;
    }

    // per-word prefix within the block
    int w = blockIdx.x * S1_BLOCK + threadIdx.x;
    unsigned m = (w < NWORDS) ? g_mask[w] : 0u;
    int c = __popc(m);
    int v = c;
    #pragma unroll
    for (int o = 1; o < 32; o <<= 1) {
        int u = __shfl_up_sync(0xffffffffu, v, o);
        if (lane >= o) v += u;
    }
    if (lane == 31) scan8[warp] = v;
    __syncthreads();
    int wbase = 0;
    #pragma unroll
    for (int k = 0; k < 8; k++) wbase += (k < warp) ? scan8[k] : 0;
    int rank = s_base + wbase + (v - c);

    float4* u4 = (float4*)out_unq;
    while (m) {
        int b = __ffs(m) - 1;
        m &= m - 1;
        int key = w * 32 + b;
        int cnt = (int)g_acc[key].w;
        unsigned pk = ((unsigned)rank << 11) | (unsigned)cnt;
        g_acc[key].w = __int_as_float((int)pk);
        int k2 = key;
        int tt = k2 % NTIME; k2 /= NTIME;
        int yy = k2 % GY;    k2 /= GY;
        int xx = k2 % GX;
        int bb = k2 / GX;
        u4[rank] = make_float4((float)bb, (float)tt, (float)yy, (float)xx);
        rank++;
    }
}

// ---------------------------------------------------------------------------
// 4) Per-point features (smem-staged float4 stores) + unq_inv + tail -1 fill
//    + grid_size output.
// ---------------------------------------------------------------------------
__global__ void k_feat(const float* __restrict__ pts, float* __restrict__ out,
                       int N) {
    __shared__ float sf[256 * 9];
    int i = blockIdx.x * 256 + threadIdx.x;
    bool act = (i < N);
    float r[9] = {0, 0, 0, 0, 0, 0, 0, 0, 0};
    int rankv = 0;
    if (act) {
        const float2* p2 = (const float2*)(pts + (size_t)i * 6);
        float2 a = __ldg(p2);
        float2 b = __ldg(p2 + 1);
        float2 c = __ldg(p2 + 2);
        float x = a.y, y = b.x, z = b.y, inten = c.x;
        int cx = (int)((x + 50.0f) * 4.0f);
        int cy = (int)((y + 50.0f) * 4.0f);
        int key = (((int)a.x * GX + cx) * GY + cy) * NTIME + (int)c.y;
        float4 g = __ldg(&g_acc[key]);
        unsigned pk = (unsigned)__float_as_int(g.w);
        int cnt = (int)(pk & 2047u);
        rankv = (int)(pk >> 11);
        float inv = 1.0f / (float)cnt;
        r[0] = x; r[1] = y; r[2] = z; r[3] = inten;
        r[4] = x - g.x * inv;
        r[5] = y - g.y * inv;
        r[6] = z - g.z * inv;
        r[7] = x - ((float)cx * 0.25f - 49.875f);
        r[8] = y - ((float)cy * 0.25f - 49.875f);
    }
    #pragma unroll
    for (int j = 0; j < 9; j++) sf[threadIdx.x * 9 + j] = r[j];
    __syncthreads();

    size_t blockBase = (size_t)blockIdx.x * (256 * 9);
    if (blockBase + 256 * 9 <= (size_t)9 * N) {
        float4* o4 = (float4*)(out + blockBase);
        const float4* s4 = (const float4*)sf;
        for (int t = threadIdx.x; t < 576; t += 256) o4[t] = s4[t];
    } else if (act) {
        for (int j = 0; j < 9; j++) out[(size_t)i * 9 + j] = r[j];
    }

    if (act) {
        out[(size_t)13 * N + i] = (float)rankv;  // unq_inv
        if (i >= g_total)
            ((float4*)(out + (size_t)9 * N))[i] = make_float4(-1.f, -1.f, -1.f, -1.f);
        if (i == 0) {
            float* gr = out + (size_t)14 * N;
            gr[0] = 400.0f; gr[1] = 400.0f; gr[2] = 1.0f;
        }
    }
}

// ---------------------------------------------------------------------------
extern "C" void kernel_launch(void* const* d_in, const int* in_sizes, int n_in,
                              void* d_out, int out_size) {
    const float* pts = (const float*)d_in[0];
    float* out = (float*)d_out;
    int N = in_sizes[0] / 6;
    int nPair = (N + 1) / 2;

    k_init<<<NKEYS / 256, 256>>>();
    k_accum<<<(nPair + 255) / 256, 256>>>(pts, N);
    k_scan1<<<NS1, S1_BLOCK>>>();
    k_scan3<<<NS1, S1_BLOCK>>>(out + (size_t)9 * N);
    k_feat<<<(N + 255) / 256, 256>>>(pts, out, N);
}